// round 8
// baseline (speedup 1.0000x reference)
#include <cuda_runtime.h>
#include <cuda_bf16.h>
#include <cstdint>

// ---------------- problem constants ----------------
#define DD   1024
#define EE   8
#define HH   4096
#define OO   1024
#define NTOK 4096
#define NPAIR (NTOK * 2)
#define ROWS_CAP (NPAIR + EE * 128)   // 9216

// ---------------- GEMM tile config ----------------
#define BM 128
#define BN 128
#define BKB 64       // K-chunk in int8 bytes (2 x k32 mma steps)
#define RWW 20       // smem row pitch in uint32 (16 data words + 4 pad; conflict-free)

// ---------------- asm helpers ----------------
__device__ __forceinline__ void mma_s8(int* c, const uint32_t* a, const uint32_t* b) {
    asm volatile("mma.sync.aligned.m16n8k32.row.col.s32.s8.s8.s32 "
                 "{%0,%1,%2,%3}, {%4,%5,%6,%7}, {%8,%9}, {%0,%1,%2,%3};"
                 : "+r"(c[0]), "+r"(c[1]), "+r"(c[2]), "+r"(c[3])
                 : "r"(a[0]), "r"(a[1]), "r"(a[2]), "r"(a[3]), "r"(b[0]), "r"(b[1]));
}

// ---------------- scratch (static device globals; device-code access ONLY) ----------------
__device__ int   g_counts[EE];
__device__ int   g_cursor[EE];
__device__ int   g_off[EE + 1];
__device__ int   g_top_idx[NPAIR];
__device__ float g_top_w[NPAIR];
__device__ int   g_row_token[ROWS_CAP];
__device__ int   g_row_of_pair[NPAIR];
__device__ __align__(16) float g_wtmp[(size_t)EE * HH * DD];      // transpose scratch (fp32)
__device__ __align__(16) float g_hf[(size_t)ROWS_CAP * HH];       // hidden fp32
__device__ __align__(16) float g_y[(size_t)ROWS_CAP * OO];
__device__ __align__(16) signed char g_xqh[(size_t)NTOK * DD];
__device__ __align__(16) signed char g_xql[(size_t)NTOK * DD];
__device__ __align__(16) signed char g_hqh[(size_t)ROWS_CAP * HH];
__device__ __align__(16) signed char g_hql[(size_t)ROWS_CAP * HH];
__device__ __align__(16) signed char g_w1qh[(size_t)EE * HH * DD];  // [E][H][D]
__device__ __align__(16) signed char g_w1ql[(size_t)EE * HH * DD];
__device__ __align__(16) signed char g_w2qh[(size_t)EE * OO * HH];  // [E][O][H]
__device__ __align__(16) signed char g_w2ql[(size_t)EE * OO * HH];
__device__ float g_sxa[NTOK];
__device__ float g_shr[ROWS_CAP];
__device__ float g_sw1[EE * HH];
__device__ float g_sw2[EE * OO];

// ---------------- small kernels ----------------
__global__ void init_kernel() {
    int t = threadIdx.x;
    if (t < EE) g_counts[t] = 0;
}

__global__ void router_kernel(const float* __restrict__ x,
                              const float* __restrict__ Wg,
                              const float* __restrict__ bg) {
    __shared__ float sWg[DD * EE];
    int tid = threadIdx.x;
    for (int i = tid * 4; i < DD * EE; i += blockDim.x * 4)
        *(float4*)&sWg[i] = *(const float4*)&Wg[i];
    __syncthreads();

    int warp = tid >> 5, lane = tid & 31;
    int n = blockIdx.x * 8 + warp;
    const float* xr = x + (size_t)n * DD;

    float acc[EE];
#pragma unroll
    for (int e = 0; e < EE; e++) acc[e] = 0.f;
    for (int d = lane; d < DD; d += 32) {
        float xv = xr[d];
#pragma unroll
        for (int e = 0; e < EE; e++) acc[e] += xv * sWg[d * EE + e];
    }
#pragma unroll
    for (int e = 0; e < EE; e++)
#pragma unroll
        for (int s = 16; s; s >>= 1) acc[e] += __shfl_xor_sync(0xffffffffu, acc[e], s);

    if (lane == 0) {
        float m = -1e30f;
#pragma unroll
        for (int e = 0; e < EE; e++) { acc[e] += bg[e]; m = fmaxf(m, acc[e]); }
        float s = 0.f;
#pragma unroll
        for (int e = 0; e < EE; e++) { acc[e] = __expf(acc[e] - m); s += acc[e]; }
        float inv = 1.f / s;
        int i0 = 0; float p0 = acc[0];
#pragma unroll
        for (int e = 1; e < EE; e++) if (acc[e] > p0) { p0 = acc[e]; i0 = e; }
        int i1 = -1; float p1 = -1.f;
#pragma unroll
        for (int e = 0; e < EE; e++) if (e != i0 && acc[e] > p1) { p1 = acc[e]; i1 = e; }

        g_top_idx[2 * n]     = i0; g_top_w[2 * n]     = p0 * inv;
        g_top_idx[2 * n + 1] = i1; g_top_w[2 * n + 1] = p1 * inv;
        atomicAdd(&g_counts[i0], 1);
        atomicAdd(&g_counts[i1], 1);
    }
}

__global__ void scan_kernel() {
    int off = 0;
    for (int e = 0; e < EE; e++) {
        g_off[e] = off;
        g_cursor[e] = off;
        off += (g_counts[e] + 127) & ~127;
    }
    g_off[EE] = off;
}

__global__ void scatter_kernel() {
    int p = blockIdx.x * blockDim.x + threadIdx.x;
    if (p >= NPAIR) return;
    int e = g_top_idx[p];
    int pos = atomicAdd(&g_cursor[e], 1);
    g_row_token[pos] = p >> 1;
    g_row_of_pair[p] = pos;
}

// Transpose fp32: W [E][R][C] (C contiguous) -> g_wtmp [E][C][R]
__global__ void transpose_kernel(const float* __restrict__ W, int R, int C) {
    __shared__ float t[32][33];
    int e = blockIdx.z;
    int c0 = blockIdx.x * 32, r0 = blockIdx.y * 32;
    const float* Wp = W + (size_t)e * R * C;
    int tid = threadIdx.x;
#pragma unroll
    for (int i = 0; i < 4; i++) {
        int idx = tid + 256 * i;
        int rr = idx >> 5, cc = idx & 31;
        t[rr][cc] = Wp[(size_t)(r0 + rr) * C + c0 + cc];
    }
    __syncthreads();
#pragma unroll
    for (int i = 0; i < 4; i++) {
        int idx = tid + 256 * i;
        int rr = idx >> 5, cc = idx & 31;
        g_wtmp[((size_t)e * C + c0 + rr) * (size_t)R + r0 + cc] = t[cc][rr];
    }
}

// Per-row 2-level int8 quantization. SEL: 0=x(arg), 1=W1(g_wtmp), 2=W2(g_wtmp), 3=h(g_hf)
template <int K, int SEL>
__global__ __launch_bounds__(128) void quant_rows(const float* __restrict__ xsrc) {
    int row = blockIdx.x;
    const float* src;
    signed char* dh; signed char* dl; float* sc;
    if (SEL == 0)      { src = xsrc  + (size_t)row * K; dh = g_xqh;  dl = g_xql;  sc = g_sxa; }
    else if (SEL == 1) { src = g_wtmp + (size_t)row * K; dh = g_w1qh; dl = g_w1ql; sc = g_sw1; }
    else if (SEL == 2) { src = g_wtmp + (size_t)row * K; dh = g_w2qh; dl = g_w2ql; sc = g_sw2; }
    else               { if (row >= g_off[EE]) return;
                         src = g_hf  + (size_t)row * K; dh = g_hqh;  dl = g_hql;  sc = g_shr; }

    constexpr int NV = K / 512;          // float4 per thread
    const int tid = threadIdx.x;
    float4 v[NV];
    float mx = 0.f;
#pragma unroll
    for (int i = 0; i < NV; i++) {
        v[i] = *(const float4*)(src + (size_t)(tid + i * 128) * 4);
        mx = fmaxf(mx, fmaxf(fmaxf(fabsf(v[i].x), fabsf(v[i].y)),
                             fmaxf(fabsf(v[i].z), fabsf(v[i].w))));
    }
#pragma unroll
    for (int s = 16; s; s >>= 1) mx = fmaxf(mx, __shfl_xor_sync(0xffffffffu, mx, s));
    __shared__ float wred[4];
    __shared__ float sInv;
    if ((tid & 31) == 0) wred[tid >> 5] = mx;
    __syncthreads();
    if (tid == 0) {
        float m = fmaxf(fmaxf(wred[0], wred[1]), fmaxf(wred[2], wred[3]));
        m = fmaxf(m, 1e-20f);
        sc[row] = m * (1.f / 127.f);
        sInv = 127.f / m;
    }
    __syncthreads();
    const float inv = sInv;
#pragma unroll
    for (int i = 0; i < NV; i++) {
        float vv[4] = {v[i].x, v[i].y, v[i].z, v[i].w};
        uint32_t ph = 0, pl = 0;
#pragma unroll
        for (int q = 0; q < 4; q++) {
            float f = vv[q] * inv;
            float fh = rintf(f);
            int qh = (int)fh;
            int ql = (int)rintf((f - fh) * 128.f);
            ph |= ((uint32_t)qh & 255u) << (q * 8);
            pl |= ((uint32_t)ql & 255u) << (q * 8);
        }
        size_t off = (size_t)row * K + (size_t)(tid + i * 128) * 4;
        *(uint32_t*)(dh + off) = ph;
        *(uint32_t*)(dl + off) = pl;
    }
}

// ---------------- int8 grouped GEMM (2-split Ozaki, 3 integer products) ----------------
// GEMM1: A = gathered g_xq*, B = g_w1q*, out = relu(z) fp32 -> g_hf
// GEMM2: A = g_hq* rows,     B = g_w2q*, out = fp32 g_y
template <int KTOT, int NOUTT, bool GEMM1>
__global__ __launch_bounds__(256, 1) void moe_gemm_i8(const float* __restrict__ bias) {
    const signed char* __restrict__ Aqh = GEMM1 ? g_xqh : g_hqh;
    const signed char* __restrict__ Aql = GEMM1 ? g_xql : g_hql;
    const signed char* __restrict__ Bqh = GEMM1 ? g_w1qh : g_w2qh;
    const signed char* __restrict__ Bql = GEMM1 ? g_w1ql : g_w2ql;
    const float* __restrict__ sBv = GEMM1 ? g_sw1 : g_sw2;

    __shared__ uint32_t sAh[BM][RWW];
    __shared__ uint32_t sAl[BM][RWW];
    __shared__ uint32_t sBh[BN][RWW];
    __shared__ uint32_t sBl[BN][RWW];
    __shared__ int stok[BM];

    const int tid = threadIdx.x;
    const int row0 = blockIdx.y * BM;
    if (row0 >= g_off[EE]) return;
    int e = 0;
#pragma unroll
    for (int i = 1; i < EE; i++) if (row0 >= g_off[i]) e = i;
    const int valid = g_off[e] + g_counts[e] - row0;
    const int n0 = blockIdx.x * BN;

    if (GEMM1) {
        if (tid < BM) stok[tid] = (tid < valid) ? g_row_token[row0 + tid] : -1;
        __syncthreads();
    }

    // loader: thread covers rows rr and rr+64, 16B chunk ch, for all 4 buffers
    const int rr = tid >> 2, ch = tid & 3;
    const int r1 = rr + 64;
    long ta0, ta1; bool ok0, ok1;
    if (GEMM1) {
        int t0 = stok[rr], t1 = stok[r1];
        ok0 = (t0 >= 0); ok1 = (t1 >= 0);
        ta0 = ok0 ? t0 : 0; ta1 = ok1 ? t1 : 0;
    } else {
        ta0 = row0 + rr; ta1 = row0 + r1; ok0 = ok1 = true;
    }
    const signed char* pAh0 = Aqh + (size_t)ta0 * KTOT + ch * 16;
    const signed char* pAh1 = Aqh + (size_t)ta1 * KTOT + ch * 16;
    const signed char* pAl0 = Aql + (size_t)ta0 * KTOT + ch * 16;
    const signed char* pAl1 = Aql + (size_t)ta1 * KTOT + ch * 16;
    const size_t bb = (size_t)(e * NOUTT + n0);
    const signed char* pBh0 = Bqh + (bb + rr) * KTOT + ch * 16;
    const signed char* pBh1 = Bqh + (bb + r1) * KTOT + ch * 16;
    const signed char* pBl0 = Bql + (bb + rr) * KTOT + ch * 16;
    const signed char* pBl1 = Bql + (bb + r1) * KTOT + ch * 16;

    const int lane = tid & 31, wid = tid >> 5;
    const int wm = (wid >> 2) * 64, wn = (wid & 3) * 32;
    const int gid = lane >> 2, tg = lane & 3;

    int hh[4][4][4], cx[4][4][4];
#pragma unroll
    for (int i = 0; i < 4; i++)
#pragma unroll
        for (int j = 0; j < 4; j++)
#pragma unroll
            for (int q = 0; q < 4; q++) { hh[i][j][q] = 0; cx[i][j][q] = 0; }

    const int NC = KTOT / BKB;
    const uint4 z4 = make_uint4(0u, 0u, 0u, 0u);
    uint4 pa[4], pb[4];
    pa[0] = ok0 ? *(const uint4*)pAh0 : z4;
    pa[1] = ok1 ? *(const uint4*)pAh1 : z4;
    pa[2] = ok0 ? *(const uint4*)pAl0 : z4;
    pa[3] = ok1 ? *(const uint4*)pAl1 : z4;
    pb[0] = *(const uint4*)pBh0;
    pb[1] = *(const uint4*)pBh1;
    pb[2] = *(const uint4*)pBl0;
    pb[3] = *(const uint4*)pBl1;

#pragma unroll 1
    for (int c = 0; c < NC; c++) {
        __syncthreads();   // previous iter's smem reads done before overwrite
        *(uint4*)&sAh[rr][ch * 4] = pa[0];
        *(uint4*)&sAh[r1][ch * 4] = pa[1];
        *(uint4*)&sAl[rr][ch * 4] = pa[2];
        *(uint4*)&sAl[r1][ch * 4] = pa[3];
        *(uint4*)&sBh[rr][ch * 4] = pb[0];
        *(uint4*)&sBh[r1][ch * 4] = pb[1];
        *(uint4*)&sBl[rr][ch * 4] = pb[2];
        *(uint4*)&sBl[r1][ch * 4] = pb[3];
        __syncthreads();
        if (c + 1 < NC) {  // prefetch next K-slab into regs (hidden by MMAs)
            size_t ko = (size_t)(c + 1) * BKB;
            pa[0] = ok0 ? *(const uint4*)(pAh0 + ko) : z4;
            pa[1] = ok1 ? *(const uint4*)(pAh1 + ko) : z4;
            pa[2] = ok0 ? *(const uint4*)(pAl0 + ko) : z4;
            pa[3] = ok1 ? *(const uint4*)(pAl1 + ko) : z4;
            pb[0] = *(const uint4*)(pBh0 + ko);
            pb[1] = *(const uint4*)(pBh1 + ko);
            pb[2] = *(const uint4*)(pBl0 + ko);
            pb[3] = *(const uint4*)(pBl1 + ko);
        }
#pragma unroll
        for (int kk = 0; kk < 2; kk++) {
            const int kb = kk * 8;
            // A frags (m16n8k32): a0:(gid,w tg) a1:(gid+8,tg) a2:(gid,4+tg) a3:(gid+8,4+tg)
            uint32_t au[4][4], alu[4][4];
#pragma unroll
            for (int mt = 0; mt < 4; mt++) {
                int r = wm + mt * 16 + gid;
                au[mt][0] = sAh[r][kb + tg];
                au[mt][1] = sAh[r + 8][kb + tg];
                au[mt][2] = sAh[r][kb + 4 + tg];
                au[mt][3] = sAh[r + 8][kb + 4 + tg];
                alu[mt][0] = sAl[r][kb + tg];
                alu[mt][1] = sAl[r + 8][kb + tg];
                alu[mt][2] = sAl[r][kb + 4 + tg];
                alu[mt][3] = sAl[r + 8][kb + 4 + tg];
            }
            // B frags: b0:(k word tg, n gid) b1:(4+tg, gid) in [n][k] storage
            uint32_t bu[4][2], blu[4][2];
#pragma unroll
            for (int nt = 0; nt < 4; nt++) {
                int r = wn + nt * 8 + gid;
                bu[nt][0] = sBh[r][kb + tg];
                bu[nt][1] = sBh[r][kb + 4 + tg];
                blu[nt][0] = sBl[r][kb + tg];
                blu[nt][1] = sBl[r][kb + 4 + tg];
            }
#pragma unroll
            for (int mt = 0; mt < 4; mt++)
#pragma unroll
                for (int nt = 0; nt < 4; nt++) {
                    mma_s8(hh[mt][nt], au[mt], bu[nt]);
                    mma_s8(cx[mt][nt], au[mt], blu[nt]);
                    mma_s8(cx[mt][nt], alu[mt], bu[nt]);
                }
        }
    }

    // ---------------- epilogue: z = sa*sb*(hh + cx/128) + bias ----------------
#pragma unroll
    for (int mt = 0; mt < 4; mt++) {
#pragma unroll
        for (int nt = 0; nt < 4; nt++) {
            int mm = wm + mt * 16 + gid;          // block-local row
            int m = row0 + mm;
            int n = n0 + wn + nt * 8 + 2 * tg;
            float b0 = bias[(size_t)e * NOUTT + n];
            float b1v = bias[(size_t)e * NOUTT + n + 1];
            float sb0 = sBv[(size_t)e * NOUTT + n];
            float sb1 = sBv[(size_t)e * NOUTT + n + 1];
            if (mm < valid) {
                float sa = GEMM1 ? g_sxa[stok[mm]] : g_shr[m];
                float f0 = (float)hh[mt][nt][0] + (float)cx[mt][nt][0] * 0.0078125f;
                float f1 = (float)hh[mt][nt][1] + (float)cx[mt][nt][1] * 0.0078125f;
                float z0 = f0 * (sa * sb0) + b0;
                float z1 = f1 * (sa * sb1) + b1v;
                if (GEMM1) {
                    z0 = fmaxf(z0, 0.f); z1 = fmaxf(z1, 0.f);
                    *(float2*)(g_hf + (size_t)m * NOUTT + n) = make_float2(z0, z1);
                } else {
                    *(float2*)(g_y + (size_t)m * NOUTT + n) = make_float2(z0, z1);
                }
            }
            if (mm + 8 < valid) {
                float sa = GEMM1 ? g_sxa[stok[mm + 8]] : g_shr[m + 8];
                float f2 = (float)hh[mt][nt][2] + (float)cx[mt][nt][2] * 0.0078125f;
                float f3 = (float)hh[mt][nt][3] + (float)cx[mt][nt][3] * 0.0078125f;
                float z2 = f2 * (sa * sb0) + b0;
                float z3 = f3 * (sa * sb1) + b1v;
                if (GEMM1) {
                    z2 = fmaxf(z2, 0.f); z3 = fmaxf(z3, 0.f);
                    *(float2*)(g_hf + (size_t)(m + 8) * NOUTT + n) = make_float2(z2, z3);
                } else {
                    *(float2*)(g_y + (size_t)(m + 8) * NOUTT + n) = make_float2(z2, z3);
                }
            }
        }
    }
}

// ---------------- combine ----------------
__global__ void combine_kernel(float* __restrict__ out) {
    int n = blockIdx.x;
    int r0 = g_row_of_pair[2 * n];
    int r1 = g_row_of_pair[2 * n + 1];
    float w0 = g_top_w[2 * n];
    float w1 = g_top_w[2 * n + 1];
    const float4* y0 = (const float4*)&g_y[(size_t)r0 * OO];
    const float4* y1 = (const float4*)&g_y[(size_t)r1 * OO];
    float4* o = (float4*)&out[(size_t)n * OO];
    int t = threadIdx.x;
    float4 a = y0[t], b = y1[t];
    float4 r;
    r.x = w0 * a.x + w1 * b.x;
    r.y = w0 * a.y + w1 * b.y;
    r.z = w0 * a.z + w1 * b.z;
    r.w = w0 * a.w + w1 * b.w;
    o[t] = r;
}

// ---------------- launch ----------------
extern "C" void kernel_launch(void* const* d_in, const int* in_sizes, int n_in,
                              void* d_out, int out_size) {
    const float* x  = (const float*)d_in[0];
    const float* Wg = (const float*)d_in[1];
    const float* bg = (const float*)d_in[2];
    const float* W1 = (const float*)d_in[3];
    const float* b1 = (const float*)d_in[4];
    const float* W2 = (const float*)d_in[5];
    const float* b2 = (const float*)d_in[6];
    float* out = (float*)d_out;

    init_kernel<<<1, 32>>>();
    router_kernel<<<NTOK / 8, 256>>>(x, Wg, bg);
    scan_kernel<<<1, 1>>>();
    scatter_kernel<<<NPAIR / 256, 256>>>();

    quant_rows<DD, 0><<<NTOK, 128>>>(x);
    transpose_kernel<<<dim3(HH / 32, DD / 32, EE), 256>>>(W1, DD, HH);
    quant_rows<DD, 1><<<EE * HH, 128>>>(nullptr);
    transpose_kernel<<<dim3(OO / 32, HH / 32, EE), 256>>>(W2, HH, OO);
    quant_rows<HH, 2><<<EE * OO, 128>>>(nullptr);

    moe_gemm_i8<DD, HH, true><<<dim3(HH / BN, ROWS_CAP / BM), 256>>>(b1);
    quant_rows<HH, 3><<<ROWS_CAP, 128>>>(nullptr);
    moe_gemm_i8<HH, OO, false><<<dim3(OO / BN, ROWS_CAP / BM), 256>>>(b2);

    combine_kernel<<<NTOK, 256>>>(out);
}

// round 9
// speedup vs baseline: 3.0347x; 3.0347x over previous
#include <cuda_runtime.h>
#include <cuda_bf16.h>
#include <cstdint>

// ---------------- problem constants ----------------
#define DD   1024
#define EE   8
#define HH   4096
#define OO   1024
#define NTOK 4096
#define NPAIR (NTOK * 2)
#define ROWS_CAP (NPAIR + EE * 128)   // 9216

// ---------------- GEMM tile config ----------------
#define BM 128
#define BN 128
#define BK 32
#define RWA 36       // A smem pitch (u32): 4r+tg frag loads conflict-free
#define RWB 136      // B smem pitch (u32): 136%32==8 -> 8tg+gid frag loads conflict-free

// ---------------- asm helpers ----------------
__device__ __forceinline__ void mma_tf32(float* c, const uint32_t* a, const uint32_t* b) {
    asm volatile("mma.sync.aligned.m16n8k8.row.col.f32.tf32.tf32.f32 "
                 "{%0,%1,%2,%3}, {%4,%5,%6,%7}, {%8,%9}, {%0,%1,%2,%3};"
                 : "+f"(c[0]), "+f"(c[1]), "+f"(c[2]), "+f"(c[3])
                 : "r"(a[0]), "r"(a[1]), "r"(a[2]), "r"(a[3]), "r"(b[0]), "r"(b[1]));
}
__device__ __forceinline__ uint32_t f2tf32(float v) {
    uint32_t r;
    asm("cvt.rna.tf32.f32 %0, %1;" : "=r"(r) : "f"(v));
    return r;
}
__device__ __forceinline__ uint4 cvt4(float4 v) {
    uint4 o;
    o.x = f2tf32(v.x); o.y = f2tf32(v.y);
    o.z = f2tf32(v.z); o.w = f2tf32(v.w);
    return o;
}

// ---------------- scratch (static device globals; device-code access ONLY) ----------------
__device__ int   g_counts[EE];
__device__ int   g_cursor[EE];
__device__ int   g_off[EE + 1];
__device__ int   g_top_idx[NPAIR];
__device__ float g_top_w[NPAIR];
__device__ int   g_row_token[ROWS_CAP];
__device__ int   g_row_of_pair[NPAIR];
__device__ __align__(16) float g_ht[(size_t)ROWS_CAP * HH];        // tf32-rounded hidden
__device__ __align__(16) float g_y[(size_t)ROWS_CAP * OO];

// ---------------- small kernels ----------------
__global__ void init_kernel() {
    int t = threadIdx.x;
    if (t < EE) g_counts[t] = 0;
}

__global__ void router_kernel(const float* __restrict__ x,
                              const float* __restrict__ Wg,
                              const float* __restrict__ bg) {
    __shared__ float sWg[DD * EE];
    int tid = threadIdx.x;
    for (int i = tid * 4; i < DD * EE; i += blockDim.x * 4)
        *(float4*)&sWg[i] = *(const float4*)&Wg[i];
    __syncthreads();

    int warp = tid >> 5, lane = tid & 31;
    int n = blockIdx.x * 8 + warp;
    const float* xr = x + (size_t)n * DD;

    float acc[EE];
#pragma unroll
    for (int e = 0; e < EE; e++) acc[e] = 0.f;
    for (int d = lane; d < DD; d += 32) {
        float xv = xr[d];
#pragma unroll
        for (int e = 0; e < EE; e++) acc[e] += xv * sWg[d * EE + e];
    }
#pragma unroll
    for (int e = 0; e < EE; e++)
#pragma unroll
        for (int s = 16; s; s >>= 1) acc[e] += __shfl_xor_sync(0xffffffffu, acc[e], s);

    if (lane == 0) {
        float m = -1e30f;
#pragma unroll
        for (int e = 0; e < EE; e++) { acc[e] += bg[e]; m = fmaxf(m, acc[e]); }
        float s = 0.f;
#pragma unroll
        for (int e = 0; e < EE; e++) { acc[e] = __expf(acc[e] - m); s += acc[e]; }
        float inv = 1.f / s;
        int i0 = 0; float p0 = acc[0];
#pragma unroll
        for (int e = 1; e < EE; e++) if (acc[e] > p0) { p0 = acc[e]; i0 = e; }
        int i1 = -1; float p1 = -1.f;
#pragma unroll
        for (int e = 0; e < EE; e++) if (e != i0 && acc[e] > p1) { p1 = acc[e]; i1 = e; }

        g_top_idx[2 * n]     = i0; g_top_w[2 * n]     = p0 * inv;
        g_top_idx[2 * n + 1] = i1; g_top_w[2 * n + 1] = p1 * inv;
        atomicAdd(&g_counts[i0], 1);
        atomicAdd(&g_counts[i1], 1);
    }
}

__global__ void scan_kernel() {
    int off = 0;
    for (int e = 0; e < EE; e++) {
        g_off[e] = off;
        g_cursor[e] = off;
        off += (g_counts[e] + 127) & ~127;
    }
    g_off[EE] = off;
}

__global__ void scatter_kernel() {
    int p = blockIdx.x * blockDim.x + threadIdx.x;
    if (p >= NPAIR) return;
    int e = g_top_idx[p];
    int pos = atomicAdd(&g_cursor[e], 1);
    g_row_token[pos] = p >> 1;
    g_row_of_pair[p] = pos;
}

// ---------------- TF32 grouped GEMM, fused on-the-fly rounding ----------------
// A (fp32) and B (fp32 weights [E][K][N], N contiguous) are read raw; tf32
// rounding happens in-register before the smem store. B staged [k][n] pitch 136.
// GEMM1: A = gathered x, B = W1, out = tf32-rounded relu -> g_ht.
// GEMM2: A = g_ht rows,  B = W2, out = fp32 g_y.
template <int KTOT, int NOUTT, bool GEMM1>
__global__ __launch_bounds__(256, 1) void moe_gemm(const float* __restrict__ Aarg,
                                                   const float* __restrict__ Barg,
                                                   const float* __restrict__ bias) {
    const float* __restrict__ A = GEMM1 ? Aarg : g_ht;
    const int NOUT = NOUTT;

    __shared__ __align__(16) uint32_t sA[BM][RWA];     // [m][k]
    __shared__ __align__(16) uint32_t sB[BK][RWB];     // [k][n]
    __shared__ int stok[BM];

    const int tid = threadIdx.x;
    const int row0 = blockIdx.y * BM;
    if (row0 >= g_off[EE]) return;
    int e = 0;
#pragma unroll
    for (int i = 1; i < EE; i++) if (row0 >= g_off[i]) e = i;
    const int valid = g_off[e] + g_counts[e] - row0;
    const int n0 = blockIdx.x * BN;
    const float* __restrict__ Bbase = Barg + (size_t)e * KTOT * NOUT + n0;

    if (GEMM1) {
        if (tid < BM) stok[tid] = (tid < valid) ? g_row_token[row0 + tid] : -1;
        __syncthreads();
    }

    // A slots: id = tid + 256j (j<4): r = id>>3 (row), ch = id&7 (k-chunk of 4)
    const float* asrc[4]; uint32_t* adst[4]; bool aok[4];
    // B slots: kq = id>>5 (k-row), nq = id&31 (n-chunk of 4)
    const float* bsrc[4]; uint32_t* bdst[4];
#pragma unroll
    for (int j = 0; j < 4; j++) {
        int id = tid + 256 * j;
        int r = id >> 3, ch = id & 7;
        long arow;
        if (GEMM1) {
            int tk = stok[r];
            arow = (tk >= 0) ? tk : 0;
            aok[j] = (tk >= 0);
        } else {
            arow = row0 + r;
            aok[j] = true;
        }
        asrc[j] = A + (size_t)arow * KTOT + ch * 4;
        adst[j] = &sA[r][ch * 4];
        int kq = id >> 5, nq = id & 31;
        bsrc[j] = Bbase + (size_t)kq * NOUT + nq * 4;
        bdst[j] = &sB[kq][nq * 4];
    }

    const int lane = tid & 31, wid = tid >> 5;
    const int wm = (wid >> 2) * 64, wn = (wid & 3) * 32;
    const int gid = lane >> 2, tg = lane & 3;

    float acc[4][4][4];
#pragma unroll
    for (int i = 0; i < 4; i++)
#pragma unroll
        for (int j = 0; j < 4; j++)
#pragma unroll
            for (int q = 0; q < 4; q++) acc[i][j][q] = 0.f;

    const int NC = KTOT / BK;
    const float4 zf4 = make_float4(0.f, 0.f, 0.f, 0.f);
    float4 pa[4], pb[4];
#pragma unroll
    for (int j = 0; j < 4; j++) {
        pa[j] = aok[j] ? *(const float4*)asrc[j] : zf4;
        pb[j] = *(const float4*)bsrc[j];
    }

#pragma unroll 1
    for (int c = 0; c < NC; c++) {
        __syncthreads();   // previous iter's smem reads done before overwrite
#pragma unroll
        for (int j = 0; j < 4; j++) {
            *(uint4*)adst[j] = cvt4(pa[j]);
            *(uint4*)bdst[j] = cvt4(pb[j]);
        }
        __syncthreads();
        if (c + 1 < NC) {  // prefetch next K-slab into regs (hidden by MMAs)
            size_t ko = (size_t)(c + 1) * BK;
#pragma unroll
            for (int j = 0; j < 4; j++) {
                pa[j] = aok[j] ? *(const float4*)(asrc[j] + ko) : zf4;
                pb[j] = *(const float4*)(bsrc[j] + ko * NOUT);
            }
        }
#pragma unroll
        for (int kk = 0; kk < 4; kk++) {
            const int kb = kk * 8;   // 8 fp32 = K8 per mma step
            // A frags (m16n8k8): a0:(gid,tg) a1:(gid+8,tg) a2:(gid,tg+4) a3:(gid+8,tg+4)
            uint32_t af[4][4];
#pragma unroll
            for (int mt = 0; mt < 4; mt++) {
                int r = wm + mt * 16 + gid;
                af[mt][0] = sA[r][kb + tg];
                af[mt][1] = sA[r + 8][kb + tg];
                af[mt][2] = sA[r][kb + 4 + tg];
                af[mt][3] = sA[r + 8][kb + 4 + tg];
            }
            // B frags from [k][n]: b0 = (k=kb+tg, n), b1 = (k=kb+4+tg, n)
            uint32_t bf[4][2];
#pragma unroll
            for (int nt = 0; nt < 4; nt++) {
                int n = wn + nt * 8 + gid;
                bf[nt][0] = sB[kb + tg][n];
                bf[nt][1] = sB[kb + 4 + tg][n];
            }
#pragma unroll
            for (int mt = 0; mt < 4; mt++)
#pragma unroll
                for (int nt = 0; nt < 4; nt++)
                    mma_tf32(acc[mt][nt], af[mt], bf[nt]);
        }
    }

    // ---------------- epilogue (C frag: c0/c1 row gid cols 2tg,2tg+1; c2/c3 row gid+8) ----------------
#pragma unroll
    for (int mt = 0; mt < 4; mt++) {
#pragma unroll
        for (int nt = 0; nt < 4; nt++) {
            int mm = wm + mt * 16 + gid;          // block-local row
            int m = row0 + mm;
            int n = n0 + wn + nt * 8 + 2 * tg;
            float b0 = bias[(size_t)e * NOUT + n];
            float b1v = bias[(size_t)e * NOUT + n + 1];
            float z00 = acc[mt][nt][0] + b0, z01 = acc[mt][nt][1] + b1v;
            float z10 = acc[mt][nt][2] + b0, z11 = acc[mt][nt][3] + b1v;
            if (GEMM1) {
                z00 = fmaxf(z00, 0.f); z01 = fmaxf(z01, 0.f);
                z10 = fmaxf(z10, 0.f); z11 = fmaxf(z11, 0.f);
                if (mm < valid) {
                    uint2 o; o.x = f2tf32(z00); o.y = f2tf32(z01);
                    *(uint2*)(g_ht + (size_t)m * NOUT + n) = o;
                }
                if (mm + 8 < valid) {
                    uint2 o; o.x = f2tf32(z10); o.y = f2tf32(z11);
                    *(uint2*)(g_ht + (size_t)(m + 8) * NOUT + n) = o;
                }
            } else {
                if (mm < valid)
                    *(float2*)(g_y + (size_t)m * NOUT + n) = make_float2(z00, z01);
                if (mm + 8 < valid)
                    *(float2*)(g_y + (size_t)(m + 8) * NOUT + n) = make_float2(z10, z11);
            }
        }
    }
}

// ---------------- combine ----------------
__global__ void combine_kernel(float* __restrict__ out) {
    int n = blockIdx.x;
    int r0 = g_row_of_pair[2 * n];
    int r1 = g_row_of_pair[2 * n + 1];
    float w0 = g_top_w[2 * n];
    float w1 = g_top_w[2 * n + 1];
    const float4* y0 = (const float4*)&g_y[(size_t)r0 * OO];
    const float4* y1 = (const float4*)&g_y[(size_t)r1 * OO];
    float4* o = (float4*)&out[(size_t)n * OO];
    int t = threadIdx.x;
    float4 a = y0[t], b = y1[t];
    float4 r;
    r.x = w0 * a.x + w1 * b.x;
    r.y = w0 * a.y + w1 * b.y;
    r.z = w0 * a.z + w1 * b.z;
    r.w = w0 * a.w + w1 * b.w;
    o[t] = r;
}

// ---------------- launch ----------------
extern "C" void kernel_launch(void* const* d_in, const int* in_sizes, int n_in,
                              void* d_out, int out_size) {
    const float* x  = (const float*)d_in[0];
    const float* Wg = (const float*)d_in[1];
    const float* bg = (const float*)d_in[2];
    const float* W1 = (const float*)d_in[3];
    const float* b1 = (const float*)d_in[4];
    const float* W2 = (const float*)d_in[5];
    const float* b2 = (const float*)d_in[6];
    float* out = (float*)d_out;

    init_kernel<<<1, 32>>>();
    router_kernel<<<NTOK / 8, 256>>>(x, Wg, bg);
    scan_kernel<<<1, 1>>>();
    scatter_kernel<<<NPAIR / 256, 256>>>();

    moe_gemm<DD, HH, true><<<dim3(HH / BN, ROWS_CAP / BM), 256>>>(x, W1, b1);
    moe_gemm<HH, OO, false><<<dim3(OO / BN, ROWS_CAP / BM), 256>>>(x, W2, b2);

    combine_kernel<<<NTOK, 256>>>(out);
}